// round 5
// baseline (speedup 1.0000x reference)
#include <cuda_runtime.h>
#include <cstdint>

#define NB_GROUPS 8
#define TBL       32768            // 2^(P + N_GROUPS - 1)
#define BATCH     524288
#define N_TILES   (BATCH / 32)     // 16384 warp-tiles of 32 elements
#define BLOCKS    444              // 148 SMs * 3 blocks
#define WPB       4                // warps per block (128 threads)
#define STRIDE    (BLOCKS * WPB)   // 1776 warps, static tile striding
#define TILE_B    8192             // raw bits per tile: 32 elem * 64 int * 4B

// Dynamic smem layout (per block)
#define SM_RAW    0                               // 4 warps * 2 bufs * 8192 = 64 KB
#define SM_NIB    (65536)                         // 4 * 512 nibble bytes
#define SM_ADDR   (65536 + 2048)                  // 4 * 256 u16
#define SM_CARRY  (65536 + 4096)                  // 1792 B
#define SM_MBAR   (65536 + 4096 + 1792)           // 8 mbarriers * 8 B
#define SMEM_TOTAL (SM_MBAR + 64)

// Transposed table: [g][addr][p] -> one contiguous 32B entry per (g,addr).
__device__ float d_tpose[NB_GROUPS * TBL * 8];    // 8 MB device-global scratch

// -------------------------------------------------------------------------
// Kernel 1: transpose group_tables (8,8,32768) -> (8,32768,8)
// -------------------------------------------------------------------------
__global__ __launch_bounds__(256) void transpose_kernel(const float* __restrict__ gt) {
    int idx = blockIdx.x * blockDim.x + threadIdx.x;   // g*32768 + addr
    int g = idx >> 15;
    int a = idx & (TBL - 1);
    float v[8];
#pragma unroll
    for (int p = 0; p < 8; ++p)
        v[p] = __ldg(&gt[((g * 8 + p) << 15) + a]);    // coalesced across lanes
    float4* dst = reinterpret_cast<float4*>(d_tpose) + ((size_t)idx << 1);
    dst[0] = make_float4(v[0], v[1], v[2], v[3]);
    dst[1] = make_float4(v[4], v[5], v[6], v[7]);
}

// ---- tiny PTX helpers ----------------------------------------------------
__device__ __forceinline__ uint32_t smem_u32(const void* p) {
    uint32_t a;
    asm("{ .reg .u64 t; cvta.to.shared.u64 t, %1; cvt.u32.u64 %0, t; }"
        : "=r"(a) : "l"(p));
    return a;
}
__device__ __forceinline__ void mbar_init(uint32_t mbar) {
    asm volatile("mbarrier.init.shared.b64 [%0], 1;" :: "r"(mbar) : "memory");
}
__device__ __forceinline__ void mbar_expect_tx(uint32_t mbar, uint32_t bytes) {
    asm volatile("mbarrier.arrive.expect_tx.shared.b64 _, [%0], %1;"
                 :: "r"(mbar), "r"(bytes) : "memory");
}
__device__ __forceinline__ void mbar_wait(uint32_t mbar, uint32_t phase) {
    asm volatile(
        "{\n\t.reg .pred P;\n\t"
        "W%=:\n\t"
        "mbarrier.try_wait.parity.shared::cta.b64 P, [%0], %1;\n\t"
        "@!P bra W%=;\n\t}"
        :: "r"(mbar), "r"(phase) : "memory");
}
__device__ __forceinline__ void bulk_copy_g2s(uint32_t dst, const void* src,
                                              uint32_t bytes, uint32_t mbar) {
    asm volatile(
        "cp.async.bulk.shared::cta.global.mbarrier::complete_tx::bytes "
        "[%0], [%1], %2, [%3];"
        :: "r"(dst), "l"(src), "r"(bytes), "r"(mbar) : "memory");
}
__device__ __forceinline__ void fence_async_smem() {
    asm volatile("fence.proxy.async.shared::cta;" ::: "memory");
}

// -------------------------------------------------------------------------
// Kernel 2: persistent warps, TMA-staged bits, double-buffered per warp.
// -------------------------------------------------------------------------
__global__ __launch_bounds__(128) void mapper_kernel(
    const char* __restrict__ bits_raw,   // (B, 64) int32, viewed as bytes
    const int*  __restrict__ carry,      // (7, 256) int32 0/1
    float4*     __restrict__ out4)       // out viewed as float4
{
    extern __shared__ char smem[];
    const int t    = threadIdx.x;
    const int wid  = t >> 5;
    const int lane = t & 31;

    uint8_t*  s_carry = (uint8_t*)(smem + SM_CARRY);
    uint8_t*  s_nib   = (uint8_t*)(smem + SM_NIB) + (wid << 9);
    uint16_t* s_addr  = (uint16_t*)(smem + SM_ADDR + (wid << 9));
    const uint32_t smem_base = smem_u32(smem);

    // init mbarriers + carry LUT
    if (t < WPB * 2) mbar_init(smem_base + SM_MBAR + t * 8);
    for (int i = t; i < 7 * 256; i += 128)
        s_carry[i] = (uint8_t)carry[i];
    __syncthreads();

    const int w = blockIdx.x * WPB + wid;               // global warp id
    const uint32_t mbar0 = smem_base + SM_MBAR + (wid * 2) * 8;
    const uint32_t raw0  = smem_base + SM_RAW + (wid << 14);   // wid*16KB
    const char*    raw_p = smem + SM_RAW + (wid << 14);

    // ---- prologue: prefetch first two tiles ----
    {
        int t0 = w, t1 = w + STRIDE;
        if (lane == 0 && t0 < N_TILES) {
            mbar_expect_tx(mbar0, TILE_B);
            bulk_copy_g2s(raw0, bits_raw + (size_t)t0 * TILE_B, TILE_B, mbar0);
        }
        if (lane == 0 && t1 < N_TILES) {
            mbar_expect_tx(mbar0 + 8, TILE_B);
            bulk_copy_g2s(raw0 + TILE_B, bits_raw + (size_t)t1 * TILE_B, TILE_B, mbar0 + 8);
        }
    }

    const float4* __restrict__ tp = reinterpret_cast<const float4*>(d_tpose);

    int it = 0;
    for (int tile = w; tile < N_TILES; tile += STRIDE, ++it) {
        const int      buf   = it & 1;
        const uint32_t phase = (it >> 1) & 1;
        const uint32_t mbar  = mbar0 + buf * 8;
        const int4*    rp    = reinterpret_cast<const int4*>(raw_p + buf * TILE_B);

        mbar_wait(mbar, phase);

        // ---- Phase A: smem raw int4 -> nibble bytes (conflict-free) ----
#pragma unroll
        for (int i = 0; i < 16; ++i) {
            int L = i * 32 + lane;
            int4 v = rp[L];
            s_nib[L] = (uint8_t)((v.x << 3) | (v.y << 2) | (v.z << 1) | v.w);
        }
        __syncwarp();

        // ---- Phase B: per-lane (element = lane) addresses + carry chain ----
        {
            uint4 nb = *reinterpret_cast<const uint4*>(&s_nib[lane * 16]);
            uint32_t wv[4] = {nb.x, nb.y, nb.z, nb.w};

            uint32_t pk[4];
            uint32_t c_run = 0;
#pragma unroll
            for (int g = 0; g < 8; ++g) {
                uint32_t wb = wv[g >> 1];
                uint32_t sh = (g & 1) * 16;
                uint32_t hi = (wb >> sh) & 0xFFu;        // nibble 2g   (p=0..3)
                uint32_t lo = (wb >> (sh + 8)) & 0xFFu;  // nibble 2g+1 (p=4..7)
                uint32_t ga = (hi << 4) | lo;
                uint32_t addr = (g == 0) ? ga : ((ga << g) | c_run);
                if ((g & 1) == 0) pk[g >> 1] = addr;
                else              pk[g >> 1] |= (addr << 16);
                if (g < 7)
                    c_run = (c_run << 1) | (uint32_t)s_carry[(g << 8) + ga];
            }
            *reinterpret_cast<uint4*>(&s_addr[lane * 8]) =
                make_uint4(pk[0], pk[1], pk[2], pk[3]);
        }
        __syncwarp();

        // ---- recycle this buffer: prefetch tile + 2*STRIDE ----
        // (raw buffer fully consumed in Phase A above)
        fence_async_smem();
        {
            int tn = tile + 2 * STRIDE;
            if (lane == 0 && tn < N_TILES) {
                mbar_expect_tx(mbar, TILE_B);
                bulk_copy_g2s(raw0 + buf * TILE_B,
                              bits_raw + (size_t)tn * TILE_B, TILE_B, mbar);
            }
        }

        // ---- Phase C: cooperative gather + coalesced streaming stores ----
        float4* __restrict__ ob = out4 + (size_t)tile * 512;
#pragma unroll
        for (int i = 0; i < 16; ++i) {
            int L = i * 32 + lane;            // output float4 index in tile
            int e = L >> 4;                   // element within tile
            int g = (L >> 1) & 7;             // group
            int h = L & 1;                    // half of the 32B entry
            uint32_t addr = s_addr[(e << 3) + g];
            float4 val = __ldcg(&tp[((uint32_t)g << 16) | (addr << 1) | (uint32_t)h]);
            __stcs(&ob[L], val);              // evict-first: keep table in L2
        }
        __syncwarp();   // all lanes done with s_addr/s_nib before next iter
    }
}

// -------------------------------------------------------------------------
extern "C" void kernel_launch(void* const* d_in, const int* in_sizes, int n_in,
                              void* d_out, int out_size) {
    const char*  bits  = (const char*)d_in[0];       // (B, 64) int32
    const float* gt    = (const float*)d_in[1];      // (8, 8, 32768) f32
    const int*   carry = (const int*)d_in[2];        // (7, 256) int32
    float4*      out4  = (float4*)d_out;             // (B, 64) f32

    (void)in_sizes; (void)n_in; (void)out_size;

    static bool attr_set = false;
    if (!attr_set) {
        cudaFuncSetAttribute(mapper_kernel,
                             cudaFuncAttributeMaxDynamicSharedMemorySize,
                             SMEM_TOTAL);
        attr_set = true;
    }

    transpose_kernel<<<(NB_GROUPS * TBL) / 256, 256>>>(gt);
    mapper_kernel<<<BLOCKS, 128, SMEM_TOTAL>>>(bits, carry, out4);
}

// round 6
// speedup vs baseline: 1.0004x; 1.0004x over previous
#include <cuda_runtime.h>
#include <cstdint>

#define NB_GROUPS 8
#define TBL       32768          // 2^(P + N_GROUPS - 1)
#define BATCH     524288
#define N_TILES   (BATCH / 32)   // 16384 warp-tiles of 32 elements
#define GRID_MAP  (148 * 4)      // persistent grid, 4 blocks/SM (64-reg budget)

// Transposed table: [g][addr][p] -> each (g,addr) entry is one contiguous,
// 32B-aligned 8-float block (one L2 sector per gather).
__device__ float d_tpose[NB_GROUPS * TBL * 8];   // 8 MB device-global scratch
__device__ unsigned int d_ticket;                // warp-tile work counter

// -------------------------------------------------------------------------
// Kernel 1: transpose group_tables (8,8,32768) -> (8,32768,8); reset ticket.
// -------------------------------------------------------------------------
__global__ __launch_bounds__(256) void transpose_kernel(const float* __restrict__ gt) {
    int idx = blockIdx.x * blockDim.x + threadIdx.x;   // g*32768 + addr
    if (idx == 0) d_ticket = 0;                        // runs before mapper on-stream
    int g = idx >> 15;
    int a = idx & (TBL - 1);
    float v[8];
#pragma unroll
    for (int p = 0; p < 8; ++p)
        v[p] = __ldg(&gt[((g * 8 + p) << 15) + a]);    // coalesced across lanes
    float4* dst = reinterpret_cast<float4*>(d_tpose) + ((size_t)idx << 1);
    dst[0] = make_float4(v[0], v[1], v[2], v[3]);
    dst[1] = make_float4(v[4], v[5], v[6], v[7]);
}

// -------------------------------------------------------------------------
// Kernel 2: persistent warp-autonomous mapper, deep-MLP gather phase.
// -------------------------------------------------------------------------
__global__ __launch_bounds__(256, 4) void mapper_kernel(
    const int4* __restrict__ bits4,   // (B, 64) int32 viewed as int4
    const int*  __restrict__ carry,   // (7, 256) int32 0/1
    float4*     __restrict__ out4)    // out viewed as float4
{
    __shared__ uint8_t  s_nib[8][512];      // [warp][int4-slot] nibble bytes
    __shared__ uint16_t s_addr[8][256];     // [warp][elem*8+g] table addresses
    __shared__ uint8_t  s_carry[7 * 256];   // carry LUT (bytes)

    const int t    = threadIdx.x;
    const int wid  = t >> 5;
    const int lane = t & 31;

    for (int i = t; i < 7 * 256; i += 256)
        s_carry[i] = (uint8_t)carry[i];
    __syncthreads();

    // Per-lane constants for the gather phase:
    //   L = i*32 + lane; h = L&1 = lane&1; g = (L>>1)&7 = (lane>>1)&7;
    //   e = 2*i + (lane>>4)  -> s_addr u16 index = e*8 + g = sbase + 16*i
    const uint32_t gl    = (lane >> 1) & 7;
    const uint32_t hl    = lane & 1;
    const int      sbase = ((lane >> 4) << 3) + (int)gl;
    const float4* __restrict__ tpb =
        reinterpret_cast<const float4*>(d_tpose) + ((gl << 16) | hl);

    for (;;) {
        // ---- pull next warp-tile ----
        unsigned int tile;
        if (lane == 0) tile = atomicAdd(&d_ticket, 1u);
        tile = __shfl_sync(0xFFFFFFFFu, tile, 0);
        if (tile >= N_TILES) break;

        const int4* bp4 = bits4 + (size_t)tile * 512;   // 32 elems * 16 int4

        // ---- Phase A: 16 coalesced int4 loads -> nibble bytes in smem ----
#pragma unroll
        for (int i = 0; i < 16; ++i) {
            int L = i * 32 + lane;
            int4 v = __ldcs(&bp4[L]);
            s_nib[wid][L] = (uint8_t)((v.x << 3) | (v.y << 2) | (v.z << 1) | v.w);
        }
        __syncwarp();

        // ---- Phase B: per-lane (element = lane) addresses + carry chain ----
        {
            uint4 nb = *reinterpret_cast<const uint4*>(&s_nib[wid][lane * 16]);
            uint32_t wv[4] = {nb.x, nb.y, nb.z, nb.w};

            uint32_t pk[4];
            uint32_t c_run = 0;
#pragma unroll
            for (int g = 0; g < 8; ++g) {
                uint32_t w  = wv[g >> 1];
                uint32_t sh = (g & 1) * 16;
                uint32_t hi = (w >> sh) & 0xFFu;        // nibble 2g   (p=0..3)
                uint32_t lo = (w >> (sh + 8)) & 0xFFu;  // nibble 2g+1 (p=4..7)
                uint32_t ga = (hi << 4) | lo;
                uint32_t addr = (g == 0) ? ga : ((ga << g) | c_run);
                if ((g & 1) == 0) pk[g >> 1] = addr;
                else              pk[g >> 1] |= (addr << 16);
                if (g < 7)
                    c_run = (c_run << 1) | (uint32_t)s_carry[(g << 8) + ga];
            }
            *reinterpret_cast<uint4*>(&s_addr[wid][lane * 8]) =
                make_uint4(pk[0], pk[1], pk[2], pk[3]);
        }
        __syncwarp();

        // ---- Phase C: deep-MLP gather (batches of 8) + coalesced stores ----
        float4* __restrict__ ob = out4 + (size_t)tile * 512;
#pragma unroll
        for (int half = 0; half < 2; ++half) {
            float4 v[8];
#pragma unroll
            for (int j = 0; j < 8; ++j) {              // 8 independent gathers
                int i = half * 8 + j;
                uint32_t addr = s_addr[wid][sbase + i * 16];
                v[j] = __ldcg(&tpb[(size_t)addr << 1]);
            }
#pragma unroll
            for (int j = 0; j < 8; ++j) {              // then 8 coalesced stores
                int i = half * 8 + j;
                __stcs(&ob[i * 32 + lane], v[j]);      // evict-first
            }
        }
        __syncwarp();   // protect s_addr/s_nib against next-iteration overwrite
    }
}

// -------------------------------------------------------------------------
extern "C" void kernel_launch(void* const* d_in, const int* in_sizes, int n_in,
                              void* d_out, int out_size) {
    const int4*  bits4 = (const int4*)d_in[0];       // (B, 64) int32
    const float* gt    = (const float*)d_in[1];      // (8, 8, 32768) f32
    const int*   carry = (const int*)d_in[2];        // (7, 256) int32
    float4*      out4  = (float4*)d_out;             // (B, 64) f32

    (void)in_sizes; (void)n_in; (void)out_size;

    transpose_kernel<<<(NB_GROUPS * TBL) / 256, 256>>>(gt);
    mapper_kernel<<<GRID_MAP, 256>>>(bits4, carry, out4);
}

// round 7
// speedup vs baseline: 1.4026x; 1.4020x over previous
#include <cuda_runtime.h>
#include <cstdint>

#define NB_GROUPS 8
#define TBL       32768          // 2^(P + N_GROUPS - 1)
#define BATCH     524288
#define N_TILES   (BATCH / 32)   // 16384 warp-tiles of 32 elements
#define GRID_MAP  148            // one 1024-thread block per SM, persistent
#define NTHREADS  1024
#define NWARPS    32

// Dynamic smem layout (bytes)
#define SM_TBL     0             // staged transposed tables g0..g3: 120 KB
#define SM_CARRY   122880        // 1792 B carry LUT
#define SM_NIB     124672        // 32 warps * 512 B nibble staging
#define SM_ADDR    141056        // 32 warps * 512 B (256 u16 addrs)
#define SMEM_TOTAL 157440

// Transposed table: [g][addr][p] -> each (g,addr) entry is one contiguous,
// 32B-aligned 8-float block (one L2 sector / one smem row per gather).
__device__ float d_tpose[NB_GROUPS * TBL * 8];   // 8 MB device-global scratch
__device__ unsigned int d_ticket;                // warp-tile work counter

// -------------------------------------------------------------------------
// Kernel 1: transpose group_tables (8,8,32768) -> (8,32768,8); reset ticket.
// -------------------------------------------------------------------------
__global__ __launch_bounds__(256) void transpose_kernel(const float* __restrict__ gt) {
    int idx = blockIdx.x * blockDim.x + threadIdx.x;   // g*32768 + addr
    if (idx == 0) d_ticket = 0;                        // runs before mapper on-stream
    int g = idx >> 15;
    int a = idx & (TBL - 1);
    float v[8];
#pragma unroll
    for (int p = 0; p < 8; ++p)
        v[p] = __ldg(&gt[((g * 8 + p) << 15) + a]);    // coalesced across lanes
    float4* dst = reinterpret_cast<float4*>(d_tpose) + ((size_t)idx << 1);
    dst[0] = make_float4(v[0], v[1], v[2], v[3]);
    dst[1] = make_float4(v[4], v[5], v[6], v[7]);
}

// -------------------------------------------------------------------------
// Kernel 2: persistent mapper; groups 0-3 gathered from SMEM, 4-7 from L2.
// -------------------------------------------------------------------------
__global__ __launch_bounds__(NTHREADS, 1) void mapper_kernel(
    const int4* __restrict__ bits4,   // (B, 64) int32 viewed as int4
    const int*  __restrict__ carry,   // (7, 256) int32 0/1
    float4*     __restrict__ out4)    // out viewed as float4
{
    extern __shared__ char smem[];
    uint8_t*  s_carry = (uint8_t*)(smem + SM_CARRY);

    const int t    = threadIdx.x;
    const int wid  = t >> 5;
    const int lane = t & 31;

    uint8_t*  s_nib  = (uint8_t*) (smem + SM_NIB)  + (wid << 9);
    uint16_t* s_addr = (uint16_t*)(smem + SM_ADDR + (wid << 9));

    // ---- stage carry LUT + transposed tables for groups 0..3 (120 KB) ----
    for (int i = t; i < 7 * 256; i += NTHREADS)
        s_carry[i] = (uint8_t)carry[i];
    {
        float4*       st4 = (float4*)(smem + SM_TBL);
        const float4* tp4 = (const float4*)d_tpose;
        const int pre4[4] = {0, 512, 1536, 3584};     // float4 prefix per group
#pragma unroll
        for (int g = 0; g < 4; ++g) {
            int cnt = 512 << g;                       // 2^(9+g) float4s
            for (int j = t; j < cnt; j += NTHREADS)
                st4[pre4[g] + j] = tp4[(g << 16) + j];
        }
    }
    __syncthreads();

    // ---- per-lane gather constants ----
    // L = i*32 + lane; h = lane&1; g = (lane>>1)&7; addr slot = sbase + 16*i
    const uint32_t gl    = (lane >> 1) & 7;
    const uint32_t hl    = lane & 1;
    const int      sbase = ((lane >> 4) << 3) + (int)gl;
    const bool     use_s = (gl < 4);
    const int pre_b[4] = {0, 8192, 24576, 57344};     // byte prefix per group
    // smem side: entry (gl,addr) half hl at  SM_TBL + pre_b[gl] + addr*32 + hl*16
    const char* sgather = smem + SM_TBL + pre_b[gl & 3] + (hl << 4);
    // global side: float4 index ((gl<<15)+addr)*2 + hl
    const float4* __restrict__ tpb =
        reinterpret_cast<const float4*>(d_tpose) + ((gl << 16) | hl);

    for (;;) {
        // ---- pull next warp-tile ----
        unsigned int tile;
        if (lane == 0) tile = atomicAdd(&d_ticket, 1u);
        tile = __shfl_sync(0xFFFFFFFFu, tile, 0);
        if (tile >= N_TILES) break;

        const int4* bp4 = bits4 + (size_t)tile * 512;   // 32 elems * 16 int4

        // ---- Phase A: 16 coalesced int4 loads -> nibble bytes in smem ----
#pragma unroll
        for (int i = 0; i < 16; ++i) {
            int L = i * 32 + lane;
            int4 v = __ldcs(&bp4[L]);
            s_nib[L] = (uint8_t)((v.x << 3) | (v.y << 2) | (v.z << 1) | v.w);
        }
        __syncwarp();

        // ---- Phase B: per-lane (element = lane) addresses + carry chain ----
        {
            uint4 nb = *reinterpret_cast<const uint4*>(&s_nib[lane * 16]);
            uint32_t wv[4] = {nb.x, nb.y, nb.z, nb.w};

            uint32_t pk[4];
            uint32_t c_run = 0;
#pragma unroll
            for (int g = 0; g < 8; ++g) {
                uint32_t w  = wv[g >> 1];
                uint32_t sh = (g & 1) * 16;
                uint32_t hi = (w >> sh) & 0xFFu;        // nibble 2g   (p=0..3)
                uint32_t lo = (w >> (sh + 8)) & 0xFFu;  // nibble 2g+1 (p=4..7)
                uint32_t ga = (hi << 4) | lo;
                uint32_t addr = (g == 0) ? ga : ((ga << g) | c_run);
                if ((g & 1) == 0) pk[g >> 1] = addr;
                else              pk[g >> 1] |= (addr << 16);
                if (g < 7)
                    c_run = (c_run << 1) | (uint32_t)s_carry[(g << 8) + ga];
            }
            *reinterpret_cast<uint4*>(&s_addr[lane * 8]) =
                make_uint4(pk[0], pk[1], pk[2], pk[3]);
        }
        __syncwarp();

        // ---- Phase C: hybrid gather (LDS for g<4, LDG for g>=4) + stores ----
        float4* __restrict__ ob = out4 + (size_t)tile * 512;
#pragma unroll
        for (int i = 0; i < 16; ++i) {
            uint32_t addr = s_addr[sbase + i * 16];
            float4 v;
            if (use_s)
                v = *reinterpret_cast<const float4*>(sgather + ((size_t)addr << 5));
            else
                v = __ldg(&tpb[(size_t)addr << 1]);
            __stcs(&ob[i * 32 + lane], v);              // evict-first
        }
        __syncwarp();   // protect s_addr/s_nib against next-iteration overwrite
    }
}

// -------------------------------------------------------------------------
extern "C" void kernel_launch(void* const* d_in, const int* in_sizes, int n_in,
                              void* d_out, int out_size) {
    const int4*  bits4 = (const int4*)d_in[0];       // (B, 64) int32
    const float* gt    = (const float*)d_in[1];      // (8, 8, 32768) f32
    const int*   carry = (const int*)d_in[2];        // (7, 256) int32
    float4*      out4  = (float4*)d_out;             // (B, 64) f32

    (void)in_sizes; (void)n_in; (void)out_size;

    static bool attr_set = false;
    if (!attr_set) {
        cudaFuncSetAttribute(mapper_kernel,
                             cudaFuncAttributeMaxDynamicSharedMemorySize,
                             SMEM_TOTAL);
        attr_set = true;
    }

    transpose_kernel<<<(NB_GROUPS * TBL) / 256, 256>>>(gt);
    mapper_kernel<<<GRID_MAP, NTHREADS, SMEM_TOTAL>>>(bits4, carry, out4);
}